// round 1
// baseline (speedup 1.0000x reference)
#include <cuda_runtime.h>

#define HID 256
#define PPB 8          // points per block
#define TPB 256

// out-of-line helper: swish value + 1st + 2nd derivative factors
__device__ __forceinline__ void swish_derivs(float z, float& s, float& sp, float& spp) {
    float sig = 1.0f / (1.0f + __expf(-z));
    float om  = 1.0f - sig;
    s   = z * sig;
    sp  = sig * (1.0f + z * om);
    spp = sig * om * (2.0f + z * (1.0f - 2.0f * sig));
}

__global__ __launch_bounds__(TPB, 2)
void pinn_burgers2d_kernel(
    const float* __restrict__ x, const float* __restrict__ y,
    const float* __restrict__ t, const float* __restrict__ nu,
    const float* __restrict__ W0, const float* __restrict__ b0,
    const float* __restrict__ W1, const float* __restrict__ b1,
    const float* __restrict__ W2, const float* __restrict__ b2,
    const float* __restrict__ W3, const float* __restrict__ b3,
    const float* __restrict__ W4, const float* __restrict__ b4,
    float* __restrict__ out, int N)
{
    // state: [point][channel][neuron]; channels: 0=h,1=hx,2=hy,3=ht,4=hxx,5=hyy
    __shared__ float S[PPB][6][HID];   // 48 KB

    const int j    = threadIdx.x;          // neuron owned by this thread
    const int base = blockIdx.x * PPB;

    // ---------------- layer 0: (4 -> 256) + swish ----------------
    {
        const float w0 = W0[0 * HID + j];
        const float w1 = W0[1 * HID + j];
        const float w2 = W0[2 * HID + j];
        const float w3 = W0[3 * HID + j];
        const float bb = b0[j];
        #pragma unroll
        for (int p = 0; p < PPB; p++) {
            int idx = base + p; if (idx >= N) idx = N - 1;
            // input scaling: x,y ranges [-1,1] -> identity; t in [0,1]; nu in [0.01,0.1]
            const float xs = x[idx];
            const float ys = y[idx];
            const float ts = 2.0f * t[idx] - 1.0f;
            const float ns = 2.0f * (nu[idx] - 0.01f) * (1.0f / 0.09f) - 1.0f;
            float z  = fmaf(xs, w0, fmaf(ys, w1, fmaf(ts, w2, fmaf(ns, w3, bb))));
            float zx = w0, zy = w1, zt = 2.0f * w2;   // zxx = zyy = 0
            float s, sp, spp;
            swish_derivs(z, s, sp, spp);
            S[p][0][j] = s;
            S[p][1][j] = sp * zx;
            S[p][2][j] = sp * zy;
            S[p][3][j] = sp * zt;
            S[p][4][j] = spp * zx * zx;
            S[p][5][j] = spp * zy * zy;
        }
    }
    __syncthreads();

    // ---------------- hidden layers 1..3: (256 -> 256) + swish ----------------
    #pragma unroll 1
    for (int l = 0; l < 3; l++) {
        const float* __restrict__ W = (l == 0) ? W1 : (l == 1) ? W2 : W3;
        const float* __restrict__ b = (l == 0) ? b1 : (l == 1) ? b2 : b3;

        float acc[PPB][6];
        #pragma unroll
        for (int p = 0; p < PPB; p++)
            #pragma unroll
            for (int s = 0; s < 6; s++) acc[p][s] = 0.0f;

        #pragma unroll 1
        for (int k = 0; k < HID; k += 4) {
            const float w0 = __ldg(&W[(k + 0) * HID + j]);
            const float w1 = __ldg(&W[(k + 1) * HID + j]);
            const float w2 = __ldg(&W[(k + 2) * HID + j]);
            const float w3 = __ldg(&W[(k + 3) * HID + j]);
            #pragma unroll
            for (int p = 0; p < PPB; p++) {
                #pragma unroll
                for (int s = 0; s < 6; s++) {
                    const float4 v = *reinterpret_cast<const float4*>(&S[p][s][k]);
                    acc[p][s] = fmaf(v.x, w0, fmaf(v.y, w1, fmaf(v.z, w2, fmaf(v.w, w3, acc[p][s]))));
                }
            }
        }
        const float bb = b[j];
        __syncthreads();   // all reads of S done before anyone overwrites

        #pragma unroll
        for (int p = 0; p < PPB; p++) {
            const float z   = acc[p][0] + bb;
            const float zx  = acc[p][1];
            const float zy  = acc[p][2];
            const float zt  = acc[p][3];
            const float zxx = acc[p][4];
            const float zyy = acc[p][5];
            float s, sp, spp;
            swish_derivs(z, s, sp, spp);
            S[p][0][j] = s;
            S[p][1][j] = sp * zx;
            S[p][2][j] = sp * zy;
            S[p][3][j] = sp * zt;
            S[p][4][j] = fmaf(spp, zx * zx, sp * zxx);
            S[p][5][j] = fmaf(spp, zy * zy, sp * zyy);
        }
        __syncthreads();
    }

    // ---------------- final layer (256 -> 2) + PDE residual ----------------
    // warp w handles point p = w; lanes stride over k.
    const int warp = j >> 5;
    const int lane = j & 31;

    float a[12];  // a[2*s+o]: s in {h,x,y,t,xx,yy}, o in {u,v}
    #pragma unroll
    for (int r = 0; r < 12; r++) a[r] = 0.0f;

    #pragma unroll
    for (int i = 0; i < HID / 32; i++) {
        const int k = lane + 32 * i;
        const float w0 = W4[2 * k + 0];
        const float w1 = W4[2 * k + 1];
        #pragma unroll
        for (int s = 0; s < 6; s++) {
            const float v = S[warp][s][k];
            a[2 * s + 0] = fmaf(v, w0, a[2 * s + 0]);
            a[2 * s + 1] = fmaf(v, w1, a[2 * s + 1]);
        }
    }
    #pragma unroll
    for (int r = 0; r < 12; r++) {
        #pragma unroll
        for (int off = 16; off > 0; off >>= 1)
            a[r] += __shfl_xor_sync(0xffffffffu, a[r], off);
    }

    if (lane == 0) {
        const int idx = base + warp;
        if (idx < N) {
            const float u   = a[0] + b4[0];
            const float v   = a[1] + b4[1];
            const float u_x = a[2],  v_x = a[3];
            const float u_y = a[4],  v_y = a[5];
            const float u_t = a[6],  v_t = a[7];
            const float u_xx = a[8], v_xx = a[9];
            const float u_yy = a[10], v_yy = a[11];
            const float nv = nu[idx];
            const float fu = u_t + u * u_x + v * u_y - nv * (u_xx + u_yy);
            const float fv = v_t + u * v_x + v * v_y - nv * (v_xx + v_yy);
            out[2 * idx + 0] = fu;
            out[2 * idx + 1] = fv;
        }
    }
}

extern "C" void kernel_launch(void* const* d_in, const int* in_sizes, int n_in,
                              void* d_out, int out_size) {
    const float* x  = (const float*)d_in[0];
    const float* y  = (const float*)d_in[1];
    const float* t  = (const float*)d_in[2];
    const float* nu = (const float*)d_in[3];
    const float* W0 = (const float*)d_in[4];
    const float* b0 = (const float*)d_in[5];
    const float* W1 = (const float*)d_in[6];
    const float* b1 = (const float*)d_in[7];
    const float* W2 = (const float*)d_in[8];
    const float* b2 = (const float*)d_in[9];
    const float* W3 = (const float*)d_in[10];
    const float* b3 = (const float*)d_in[11];
    const float* W4 = (const float*)d_in[12];
    const float* b4 = (const float*)d_in[13];
    float* out = (float*)d_out;

    const int N = in_sizes[0];
    const int blocks = (N + PPB - 1) / PPB;

    pinn_burgers2d_kernel<<<blocks, TPB>>>(x, y, t, nu,
                                           W0, b0, W1, b1, W2, b2, W3, b3, W4, b4,
                                           out, N);
}

// round 2
// speedup vs baseline: 1.4485x; 1.4485x over previous
#include <cuda_runtime.h>

#define HID 256
#define PPB 4          // points per block
#define TPB 128        // each thread owns neurons 2t and 2t+1

__device__ __forceinline__ void swish_derivs(float z, float& s, float& sp, float& spp) {
    float sig = 1.0f / (1.0f + __expf(-z));
    float om  = 1.0f - sig;
    s   = z * sig;
    sp  = sig * (1.0f + z * om);
    spp = sig * om * (2.0f + z * (1.0f - 2.0f * sig));
}

__global__ __launch_bounds__(TPB)
void pinn_burgers2d_kernel(
    const float* __restrict__ x, const float* __restrict__ y,
    const float* __restrict__ t, const float* __restrict__ nu,
    const float* __restrict__ W0, const float* __restrict__ b0,
    const float* __restrict__ W1, const float* __restrict__ b1,
    const float* __restrict__ W2, const float* __restrict__ b2,
    const float* __restrict__ W3, const float* __restrict__ b3,
    const float* __restrict__ W4, const float* __restrict__ b4,
    float* __restrict__ out, int N)
{
    // state: [point][channel][neuron]; channels: 0=h,1=hx,2=hy,3=ht,4=hxx,5=hyy
    __shared__ float S[PPB][6][HID];   // 24 KB

    const int tid  = threadIdx.x;       // 0..127
    const int n0   = 2 * tid;           // this thread owns neurons n0, n0+1
    const int base = blockIdx.x * PPB;

    // ---------------- layer 0: (4 -> 256) + swish ----------------
    {
        const float2 w0 = *reinterpret_cast<const float2*>(&W0[0 * HID + n0]);
        const float2 w1 = *reinterpret_cast<const float2*>(&W0[1 * HID + n0]);
        const float2 w2 = *reinterpret_cast<const float2*>(&W0[2 * HID + n0]);
        const float2 w3 = *reinterpret_cast<const float2*>(&W0[3 * HID + n0]);
        const float2 bb = *reinterpret_cast<const float2*>(&b0[n0]);
        #pragma unroll
        for (int p = 0; p < PPB; p++) {
            int idx = base + p; if (idx >= N) idx = N - 1;
            const float xs = x[idx];
            const float ys = y[idx];
            const float ts = 2.0f * t[idx] - 1.0f;
            const float ns = 2.0f * (nu[idx] - 0.01f) * (1.0f / 0.09f) - 1.0f;

            // neuron A (n0)
            {
                float z  = fmaf(xs, w0.x, fmaf(ys, w1.x, fmaf(ts, w2.x, fmaf(ns, w3.x, bb.x))));
                float zx = w0.x, zy = w1.x, zt = 2.0f * w2.x;
                float s, sp, spp; swish_derivs(z, s, sp, spp);
                S[p][0][n0] = s;
                S[p][1][n0] = sp * zx;
                S[p][2][n0] = sp * zy;
                S[p][3][n0] = sp * zt;
                S[p][4][n0] = spp * zx * zx;
                S[p][5][n0] = spp * zy * zy;
            }
            // neuron B (n0+1)
            {
                float z  = fmaf(xs, w0.y, fmaf(ys, w1.y, fmaf(ts, w2.y, fmaf(ns, w3.y, bb.y))));
                float zx = w0.y, zy = w1.y, zt = 2.0f * w2.y;
                float s, sp, spp; swish_derivs(z, s, sp, spp);
                S[p][0][n0 + 1] = s;
                S[p][1][n0 + 1] = sp * zx;
                S[p][2][n0 + 1] = sp * zy;
                S[p][3][n0 + 1] = sp * zt;
                S[p][4][n0 + 1] = spp * zx * zx;
                S[p][5][n0 + 1] = spp * zy * zy;
            }
        }
    }
    __syncthreads();

    // ---------------- hidden layers 1..3: (256 -> 256) + swish ----------------
    #pragma unroll 1
    for (int l = 0; l < 3; l++) {
        const float* __restrict__ W = (l == 0) ? W1 : (l == 1) ? W2 : W3;
        const float* __restrict__ b = (l == 0) ? b1 : (l == 1) ? b2 : b3;

        float2 acc[PPB][6];
        #pragma unroll
        for (int p = 0; p < PPB; p++)
            #pragma unroll
            for (int s = 0; s < 6; s++) acc[p][s] = make_float2(0.0f, 0.0f);

        #pragma unroll 1
        for (int k = 0; k < HID; k += 4) {
            const float2 wa = *reinterpret_cast<const float2*>(&W[(k + 0) * HID + n0]);
            const float2 wb = *reinterpret_cast<const float2*>(&W[(k + 1) * HID + n0]);
            const float2 wc = *reinterpret_cast<const float2*>(&W[(k + 2) * HID + n0]);
            const float2 wd = *reinterpret_cast<const float2*>(&W[(k + 3) * HID + n0]);
            #pragma unroll
            for (int p = 0; p < PPB; p++) {
                #pragma unroll
                for (int s = 0; s < 6; s++) {
                    const float4 v = *reinterpret_cast<const float4*>(&S[p][s][k]);
                    acc[p][s].x = fmaf(v.x, wa.x, fmaf(v.y, wb.x, fmaf(v.z, wc.x, fmaf(v.w, wd.x, acc[p][s].x))));
                    acc[p][s].y = fmaf(v.x, wa.y, fmaf(v.y, wb.y, fmaf(v.z, wc.y, fmaf(v.w, wd.y, acc[p][s].y))));
                }
            }
        }
        const float2 bb = *reinterpret_cast<const float2*>(&b[n0]);
        __syncthreads();   // all reads of S done before anyone overwrites

        #pragma unroll
        for (int p = 0; p < PPB; p++) {
            // neuron A
            float sA, spA, sppA;
            {
                const float z = acc[p][0].x + bb.x;
                swish_derivs(z, sA, spA, sppA);
            }
            // neuron B
            float sB, spB, sppB;
            {
                const float z = acc[p][0].y + bb.y;
                swish_derivs(z, sB, spB, sppB);
            }
            *reinterpret_cast<float2*>(&S[p][0][n0]) = make_float2(sA, sB);
            *reinterpret_cast<float2*>(&S[p][1][n0]) = make_float2(spA * acc[p][1].x, spB * acc[p][1].y);
            *reinterpret_cast<float2*>(&S[p][2][n0]) = make_float2(spA * acc[p][2].x, spB * acc[p][2].y);
            *reinterpret_cast<float2*>(&S[p][3][n0]) = make_float2(spA * acc[p][3].x, spB * acc[p][3].y);
            *reinterpret_cast<float2*>(&S[p][4][n0]) =
                make_float2(fmaf(sppA, acc[p][1].x * acc[p][1].x, spA * acc[p][4].x),
                            fmaf(sppB, acc[p][1].y * acc[p][1].y, spB * acc[p][4].y));
            *reinterpret_cast<float2*>(&S[p][5][n0]) =
                make_float2(fmaf(sppA, acc[p][2].x * acc[p][2].x, spA * acc[p][5].x),
                            fmaf(sppB, acc[p][2].y * acc[p][2].y, spB * acc[p][5].y));
        }
        __syncthreads();
    }

    // ---------------- final layer (256 -> 2) + PDE residual ----------------
    // warp w handles point p = w; lanes stride over k.
    const int warp = tid >> 5;      // 0..3 == point index
    const int lane = tid & 31;

    float a[12];  // a[2*s+o]: s in {h,x,y,t,xx,yy}, o in {u,v}
    #pragma unroll
    for (int r = 0; r < 12; r++) a[r] = 0.0f;

    #pragma unroll
    for (int i = 0; i < HID / 32; i++) {
        const int k = lane + 32 * i;
        const float2 w = *reinterpret_cast<const float2*>(&W4[2 * k]);
        #pragma unroll
        for (int s = 0; s < 6; s++) {
            const float v = S[warp][s][k];
            a[2 * s + 0] = fmaf(v, w.x, a[2 * s + 0]);
            a[2 * s + 1] = fmaf(v, w.y, a[2 * s + 1]);
        }
    }
    #pragma unroll
    for (int r = 0; r < 12; r++) {
        #pragma unroll
        for (int off = 16; off > 0; off >>= 1)
            a[r] += __shfl_xor_sync(0xffffffffu, a[r], off);
    }

    if (lane == 0) {
        const int idx = base + warp;
        if (idx < N) {
            const float u   = a[0] + b4[0];
            const float v   = a[1] + b4[1];
            const float u_x = a[2],  v_x = a[3];
            const float u_y = a[4],  v_y = a[5];
            const float u_t = a[6],  v_t = a[7];
            const float u_xx = a[8], v_xx = a[9];
            const float u_yy = a[10], v_yy = a[11];
            const float nv = nu[idx];
            const float fu = u_t + u * u_x + v * u_y - nv * (u_xx + u_yy);
            const float fv = v_t + u * v_x + v * v_y - nv * (v_xx + v_yy);
            out[2 * idx + 0] = fu;
            out[2 * idx + 1] = fv;
        }
    }
}

extern "C" void kernel_launch(void* const* d_in, const int* in_sizes, int n_in,
                              void* d_out, int out_size) {
    const float* x  = (const float*)d_in[0];
    const float* y  = (const float*)d_in[1];
    const float* t  = (const float*)d_in[2];
    const float* nu = (const float*)d_in[3];
    const float* W0 = (const float*)d_in[4];
    const float* b0 = (const float*)d_in[5];
    const float* W1 = (const float*)d_in[6];
    const float* b1 = (const float*)d_in[7];
    const float* W2 = (const float*)d_in[8];
    const float* b2 = (const float*)d_in[9];
    const float* W3 = (const float*)d_in[10];
    const float* b3 = (const float*)d_in[11];
    const float* W4 = (const float*)d_in[12];
    const float* b4 = (const float*)d_in[13];
    float* out = (float*)d_out;

    const int N = in_sizes[0];
    const int blocks = (N + PPB - 1) / PPB;

    pinn_burgers2d_kernel<<<blocks, TPB>>>(x, y, t, nu,
                                           W0, b0, W1, b1, W2, b2, W3, b3, W4, b4,
                                           out, N);
}

// round 3
// speedup vs baseline: 1.6471x; 1.1371x over previous
#include <cuda_runtime.h>

#define HID 256
#define PPB 4          // points per block
#define NPT 4          // neurons per thread
#define TPB 64         // TPB * NPT == HID

__device__ __forceinline__ void swish_derivs(float z, float& s, float& sp, float& spp) {
    float sig = 1.0f / (1.0f + __expf(-z));
    float om  = 1.0f - sig;
    s   = z * sig;
    sp  = sig * (1.0f + z * om);
    spp = sig * om * (2.0f + z * (1.0f - 2.0f * sig));
}

__global__ __launch_bounds__(TPB)
void pinn_burgers2d_kernel(
    const float* __restrict__ x, const float* __restrict__ y,
    const float* __restrict__ t, const float* __restrict__ nu,
    const float* __restrict__ W0, const float* __restrict__ b0,
    const float* __restrict__ W1, const float* __restrict__ b1,
    const float* __restrict__ W2, const float* __restrict__ b2,
    const float* __restrict__ W3, const float* __restrict__ b3,
    const float* __restrict__ W4, const float* __restrict__ b4,
    float* __restrict__ out, int N)
{
    // state: [point][channel][neuron]; channels: 0=h,1=hx,2=hy,3=ht,4=hxx,5=hyy
    __shared__ float S[PPB][6][HID];   // 24 KB

    const int tid  = threadIdx.x;       // 0..63
    const int n0   = NPT * tid;         // this thread owns neurons n0..n0+3
    const int base = blockIdx.x * PPB;

    // ---------------- layer 0: (4 -> 256) + swish ----------------
    {
        const float4 w0 = *reinterpret_cast<const float4*>(&W0[0 * HID + n0]);
        const float4 w1 = *reinterpret_cast<const float4*>(&W0[1 * HID + n0]);
        const float4 w2 = *reinterpret_cast<const float4*>(&W0[2 * HID + n0]);
        const float4 w3 = *reinterpret_cast<const float4*>(&W0[3 * HID + n0]);
        const float4 bb = *reinterpret_cast<const float4*>(&b0[n0]);
        const float* w0a = &w0.x; const float* w1a = &w1.x;
        const float* w2a = &w2.x; const float* w3a = &w3.x;
        const float* bba = &bb.x;
        #pragma unroll
        for (int p = 0; p < PPB; p++) {
            int idx = base + p; if (idx >= N) idx = N - 1;
            const float xs = x[idx];
            const float ys = y[idx];
            const float ts = 2.0f * t[idx] - 1.0f;
            const float ns = 2.0f * (nu[idx] - 0.01f) * (1.0f / 0.09f) - 1.0f;

            float o0[NPT], o1[NPT], o2[NPT], o3[NPT], o4[NPT], o5[NPT];
            #pragma unroll
            for (int q = 0; q < NPT; q++) {
                const float z  = fmaf(xs, w0a[q], fmaf(ys, w1a[q], fmaf(ts, w2a[q], fmaf(ns, w3a[q], bba[q]))));
                const float zx = w0a[q], zy = w1a[q], zt = 2.0f * w2a[q];
                float s, sp, spp; swish_derivs(z, s, sp, spp);
                o0[q] = s;
                o1[q] = sp * zx;
                o2[q] = sp * zy;
                o3[q] = sp * zt;
                o4[q] = spp * zx * zx;
                o5[q] = spp * zy * zy;
            }
            *reinterpret_cast<float4*>(&S[p][0][n0]) = make_float4(o0[0], o0[1], o0[2], o0[3]);
            *reinterpret_cast<float4*>(&S[p][1][n0]) = make_float4(o1[0], o1[1], o1[2], o1[3]);
            *reinterpret_cast<float4*>(&S[p][2][n0]) = make_float4(o2[0], o2[1], o2[2], o2[3]);
            *reinterpret_cast<float4*>(&S[p][3][n0]) = make_float4(o3[0], o3[1], o3[2], o3[3]);
            *reinterpret_cast<float4*>(&S[p][4][n0]) = make_float4(o4[0], o4[1], o4[2], o4[3]);
            *reinterpret_cast<float4*>(&S[p][5][n0]) = make_float4(o5[0], o5[1], o5[2], o5[3]);
        }
    }
    __syncthreads();

    // ---------------- hidden layers 1..3: (256 -> 256) + swish ----------------
    #pragma unroll 1
    for (int l = 0; l < 3; l++) {
        const float* __restrict__ W = (l == 0) ? W1 : (l == 1) ? W2 : W3;
        const float* __restrict__ b = (l == 0) ? b1 : (l == 1) ? b2 : b3;

        // acc[p][s] : float4 over this thread's 4 neurons
        float4 acc[PPB][6];
        #pragma unroll
        for (int p = 0; p < PPB; p++)
            #pragma unroll
            for (int s = 0; s < 6; s++) acc[p][s] = make_float4(0.f, 0.f, 0.f, 0.f);

        #pragma unroll 1
        for (int k = 0; k < HID; k += 4) {
            const float4 wa = *reinterpret_cast<const float4*>(&W[(k + 0) * HID + n0]);
            const float4 wb = *reinterpret_cast<const float4*>(&W[(k + 1) * HID + n0]);
            const float4 wc = *reinterpret_cast<const float4*>(&W[(k + 2) * HID + n0]);
            const float4 wd = *reinterpret_cast<const float4*>(&W[(k + 3) * HID + n0]);
            #pragma unroll
            for (int p = 0; p < PPB; p++) {
                #pragma unroll
                for (int s = 0; s < 6; s++) {
                    const float4 v = *reinterpret_cast<const float4*>(&S[p][s][k]);
                    float4& a = acc[p][s];
                    a.x = fmaf(v.x, wa.x, fmaf(v.y, wb.x, fmaf(v.z, wc.x, fmaf(v.w, wd.x, a.x))));
                    a.y = fmaf(v.x, wa.y, fmaf(v.y, wb.y, fmaf(v.z, wc.y, fmaf(v.w, wd.y, a.y))));
                    a.z = fmaf(v.x, wa.z, fmaf(v.y, wb.z, fmaf(v.z, wc.z, fmaf(v.w, wd.z, a.z))));
                    a.w = fmaf(v.x, wa.w, fmaf(v.y, wb.w, fmaf(v.z, wc.w, fmaf(v.w, wd.w, a.w))));
                }
            }
        }
        const float4 bb = *reinterpret_cast<const float4*>(&b[n0]);
        const float* bba = &bb.x;
        __syncthreads();   // all reads of S done before anyone overwrites

        #pragma unroll
        for (int p = 0; p < PPB; p++) {
            const float* az   = &acc[p][0].x;
            const float* azx  = &acc[p][1].x;
            const float* azy  = &acc[p][2].x;
            const float* azt  = &acc[p][3].x;
            const float* azxx = &acc[p][4].x;
            const float* azyy = &acc[p][5].x;
            float o0[NPT], o1[NPT], o2[NPT], o3[NPT], o4[NPT], o5[NPT];
            #pragma unroll
            for (int q = 0; q < NPT; q++) {
                float s, sp, spp;
                swish_derivs(az[q] + bba[q], s, sp, spp);
                o0[q] = s;
                o1[q] = sp * azx[q];
                o2[q] = sp * azy[q];
                o3[q] = sp * azt[q];
                o4[q] = fmaf(spp, azx[q] * azx[q], sp * azxx[q]);
                o5[q] = fmaf(spp, azy[q] * azy[q], sp * azyy[q]);
            }
            *reinterpret_cast<float4*>(&S[p][0][n0]) = make_float4(o0[0], o0[1], o0[2], o0[3]);
            *reinterpret_cast<float4*>(&S[p][1][n0]) = make_float4(o1[0], o1[1], o1[2], o1[3]);
            *reinterpret_cast<float4*>(&S[p][2][n0]) = make_float4(o2[0], o2[1], o2[2], o2[3]);
            *reinterpret_cast<float4*>(&S[p][3][n0]) = make_float4(o3[0], o3[1], o3[2], o3[3]);
            *reinterpret_cast<float4*>(&S[p][4][n0]) = make_float4(o4[0], o4[1], o4[2], o4[3]);
            *reinterpret_cast<float4*>(&S[p][5][n0]) = make_float4(o5[0], o5[1], o5[2], o5[3]);
        }
        __syncthreads();
    }

    // ---------------- final layer (256 -> 2) + PDE residual ----------------
    // 2 warps; warp w handles points w and w+2; lanes stride over k.
    const int warp = tid >> 5;      // 0..1
    const int lane = tid & 31;

    #pragma unroll
    for (int pp = 0; pp < 2; pp++) {
        const int p = warp + 2 * pp;

        float a[12];  // a[2*s+o]: s in {h,x,y,t,xx,yy}, o in {u,v}
        #pragma unroll
        for (int r = 0; r < 12; r++) a[r] = 0.0f;

        #pragma unroll
        for (int i = 0; i < HID / 32; i++) {
            const int k = lane + 32 * i;
            const float2 w = *reinterpret_cast<const float2*>(&W4[2 * k]);
            #pragma unroll
            for (int s = 0; s < 6; s++) {
                const float v = S[p][s][k];
                a[2 * s + 0] = fmaf(v, w.x, a[2 * s + 0]);
                a[2 * s + 1] = fmaf(v, w.y, a[2 * s + 1]);
            }
        }
        #pragma unroll
        for (int r = 0; r < 12; r++) {
            #pragma unroll
            for (int off = 16; off > 0; off >>= 1)
                a[r] += __shfl_xor_sync(0xffffffffu, a[r], off);
        }

        if (lane == 0) {
            const int idx = base + p;
            if (idx < N) {
                const float u   = a[0] + b4[0];
                const float v   = a[1] + b4[1];
                const float u_x = a[2],  v_x = a[3];
                const float u_y = a[4],  v_y = a[5];
                const float u_t = a[6],  v_t = a[7];
                const float u_xx = a[8], v_xx = a[9];
                const float u_yy = a[10], v_yy = a[11];
                const float nv = nu[idx];
                const float fu = u_t + u * u_x + v * u_y - nv * (u_xx + u_yy);
                const float fv = v_t + u * v_x + v * v_y - nv * (v_xx + v_yy);
                out[2 * idx + 0] = fu;
                out[2 * idx + 1] = fv;
            }
        }
    }
}

extern "C" void kernel_launch(void* const* d_in, const int* in_sizes, int n_in,
                              void* d_out, int out_size) {
    const float* x  = (const float*)d_in[0];
    const float* y  = (const float*)d_in[1];
    const float* t  = (const float*)d_in[2];
    const float* nu = (const float*)d_in[3];
    const float* W0 = (const float*)d_in[4];
    const float* b0 = (const float*)d_in[5];
    const float* W1 = (const float*)d_in[6];
    const float* b1 = (const float*)d_in[7];
    const float* W2 = (const float*)d_in[8];
    const float* b2 = (const float*)d_in[9];
    const float* W3 = (const float*)d_in[10];
    const float* b3 = (const float*)d_in[11];
    const float* W4 = (const float*)d_in[12];
    const float* b4 = (const float*)d_in[13];
    float* out = (float*)d_out;

    const int N = in_sizes[0];
    const int blocks = (N + PPB - 1) / PPB;

    pinn_burgers2d_kernel<<<blocks, TPB>>>(x, y, t, nu,
                                           W0, b0, W1, b1, W2, b2, W3, b3, W4, b4,
                                           out, N);
}